// round 15
// baseline (speedup 1.0000x reference)
#include <cuda_runtime.h>
#include <cuda_bf16.h>
#include <cstdint>

#define Bsz 4
#define SEQ 2048
#define CH  512
#define NH  8

typedef __nv_bfloat16 bf16;

__device__ bf16 g_xh[Bsz*SEQ*CH], g_xl[Bsz*SEQ*CH];
__device__ bf16 g_wqh[CH*3*CH], g_wql[CH*3*CH];        // [oc][kg=t*512+c]
__device__ bf16 g_wkh[CH*3*CH], g_wkl[CH*3*CH];
__device__ bf16 g_wvh[CH*CH],   g_wvl[CH*CH];          // [oc][c]
__device__ bf16 g_qh[Bsz*NH*SEQ*64], g_ql[Bsz*NH*SEQ*64];   // [b,h,s,d]
__device__ bf16 g_kh[Bsz*NH*SEQ*64], g_kl[Bsz*NH*SEQ*64];   // [b,h,s,d]
__device__ bf16 g_vth[Bsz*NH*64*SEQ], g_vtl[Bsz*NH*64*SEQ]; // [b,h,d,s]

__device__ __forceinline__ void split2(float x, bf16& h, bf16& l) {
    h = __float2bfloat16(x);
    l = __float2bfloat16(x - __bfloat162float(h));
}
__device__ __forceinline__ uint32_t packbf(bf16 a, bf16 b) {
    __nv_bfloat162 t(a, b);
    return *(uint32_t*)&t;
}
__device__ __forceinline__ void ldmA4(uint32_t* a, const bf16* p) {
    uint32_t addr = (uint32_t)__cvta_generic_to_shared(p);
    asm volatile("ldmatrix.sync.aligned.m8n8.x4.shared.b16 {%0,%1,%2,%3}, [%4];"
        : "=r"(a[0]), "=r"(a[1]), "=r"(a[2]), "=r"(a[3]) : "r"(addr));
}
__device__ __forceinline__ void ldmB4(uint32_t* b, const bf16* p) {
    uint32_t addr = (uint32_t)__cvta_generic_to_shared(p);
    asm volatile("ldmatrix.sync.aligned.m8n8.x4.shared.b16 {%0,%1,%2,%3}, [%4];"
        : "=r"(b[0]), "=r"(b[1]), "=r"(b[2]), "=r"(b[3]) : "r"(addr));
}
__device__ __forceinline__ void mma_bf16(float* d, const uint32_t* a, const uint32_t* b) {
    asm volatile("mma.sync.aligned.m16n8k16.row.col.f32.bf16.bf16.f32 "
        "{%0,%1,%2,%3}, {%4,%5,%6,%7}, {%8,%9}, {%0,%1,%2,%3};"
        : "+f"(d[0]), "+f"(d[1]), "+f"(d[2]), "+f"(d[3])
        : "r"(a[0]), "r"(a[1]), "r"(a[2]), "r"(a[3]), "r"(b[0]), "r"(b[1]));
}
__device__ __forceinline__ void cp_async16(void* smem, const void* gmem) {
    uint32_t s = (uint32_t)__cvta_generic_to_shared(smem);
    asm volatile("cp.async.cg.shared.global [%0], [%1], 16;" :: "r"(s), "l"(gmem));
}
__device__ __forceinline__ const bf16* b4addr(const bf16* base, int n0, int kk,
                                              int lane, int str) {
    return base + (size_t)(n0 + (lane & 7) + ((lane >> 4) << 3)) * str
                + kk + ((lane >> 3) & 1) * 8;
}
__device__ __forceinline__ void stg_cs_f2(float* p, float x, float y) {
    asm volatile("st.global.cs.v2.f32 [%0], {%1,%2};" :: "l"(p), "f"(x), "f"(y) : "memory");
}
__device__ __forceinline__ void stg_cs_z4(float* p) {
    asm volatile("st.global.cs.v4.b32 [%0], {%1,%1,%1,%1};" :: "l"(p), "r"(0u) : "memory");
}

// ---------------------------------------------------------------------------
// Prep: split x into bf16 hi/lo AND repack+split the weights — one launch.
// ---------------------------------------------------------------------------
__global__ void prep_kernel(const float* __restrict__ x,
                            const float* __restrict__ wq,
                            const float* __restrict__ wk,
                            const float* __restrict__ wv)
{
    int i = blockIdx.x * 256 + threadIdx.x;
    const int NX = Bsz * SEQ * CH;
    if (i < NX) {
        split2(x[i], g_xh[i], g_xl[i]);
        return;
    }
    i -= NX;
    if (i >= CH * 1536) return;
    const int oc = i / 1536, kg = i % 1536;
    const int c = kg & 511, t = kg >> 9;
    split2(wq[oc*1536 + c*3 + t], g_wqh[i], g_wql[i]);
    split2(wk[oc*1536 + c*3 + t], g_wkh[i], g_wkl[i]);
    if (kg < CH) split2(wv[oc*CH + kg], g_wvh[oc*CH + kg], g_wvl[oc*CH + kg]);
}

// ---------------------------------------------------------------------------
// QKV GEMM for ONE head pair hp (oc range [hp*128, hp*128+128)).
// blockIdx.y = seg (0=q,1=k,2=v). Block 128x128, Kc=32, 256 threads,
// cp.async double-buffered, x4 B-ldmatrix. bf16x3 split accum in fp32.
// ---------------------------------------------------------------------------
__global__ void __launch_bounds__(256)
qkv_gemm(int hp, const float* __restrict__ bq, const float* __restrict__ bk,
         const float* __restrict__ bv)
{
    extern __shared__ bf16 sm[];
    const int mt = blockIdx.x;
    const int seg = blockIdx.y;           // 0=q,1=k,2=v
    const int oc0 = hp * 128;
    const int gm0 = mt * 128;
    const int b = gm0 >> 11, sl0 = gm0 & 2047;
    const int KK = (seg < 2) ? 1536 : 512;
    const bf16* Wh = (seg == 0) ? g_wqh : (seg == 1) ? g_wkh : g_wvh;
    const bf16* Wl = (seg == 0) ? g_wql : (seg == 1) ? g_wkl : g_wvl;
    const float* bias = (seg == 0) ? bq : (seg == 1) ? bk : bv;

    const int tid = threadIdx.x, lane = tid & 31, wid = tid >> 5;
    const int m0 = (wid >> 1) * 32, n0 = (wid & 1) * 64;

    float acc[2][8][4];
#pragma unroll
    for (int i = 0; i < 2; i++)
#pragma unroll
        for (int j = 0; j < 8; j++)
#pragma unroll
            for (int c = 0; c < 4; c++) acc[i][j][c] = 0.f;

    auto load_stage = [&](int kt, int st) {
        bf16* Ah = sm + st * 20480;
        bf16* Al = Ah + 5120;
        bf16* Bh = Ah + 10240;
        bf16* Bl = Ah + 15360;
        const int k0 = kt * 32;
#pragma unroll
        for (int i = 0; i < 2; i++) {
            const int idx = tid + i * 256;
            const int row = idx >> 2, q8 = (idx & 3) * 8;
            int srow, c;
            if (seg < 2) { c = (k0 & 511) + q8; srow = sl0 + row + (k0 >> 9) - 2; }
            else         { c = k0 + q8;         srow = sl0 + row; }
            if (srow >= 0) {
                const size_t off = (((size_t)(b * SEQ + srow)) << 9) + c;
                cp_async16(Ah + row * 40 + q8, g_xh + off);
                cp_async16(Al + row * 40 + q8, g_xl + off);
            } else {
                const uint4 z = make_uint4(0,0,0,0);
                *(uint4*)(Ah + row * 40 + q8) = z;
                *(uint4*)(Al + row * 40 + q8) = z;
            }
            const size_t woff = (size_t)(oc0 + row) * KK + k0 + q8;
            cp_async16(Bh + row * 40 + q8, Wh + woff);
            cp_async16(Bl + row * 40 + q8, Wl + woff);
        }
    };

    auto mma_stage = [&](int st) {
        bf16* Ah = sm + st * 20480;
        bf16* Al = Ah + 5120;
        bf16* Bh = Ah + 10240;
#pragma unroll
        for (int kk = 0; kk < 32; kk += 16) {
            uint32_t fah[2][4], fal[2][4], fbh[8][2], fbl[8][2];
            const int ar = lane & 15, ac = kk + ((lane >> 4) & 1) * 8;
#pragma unroll
            for (int mf = 0; mf < 2; mf++) {
                ldmA4(fah[mf], Ah + (m0 + mf * 16 + ar) * 40 + ac);
                ldmA4(fal[mf], Al + (m0 + mf * 16 + ar) * 40 + ac);
            }
#pragma unroll
            for (int nf = 0; nf < 8; nf += 2) {
                const bf16* pb = b4addr(Bh, n0 + nf * 8, kk, lane, 40);
                ldmB4(&fbh[nf][0], pb);
                ldmB4(&fbl[nf][0], pb + 5120);
            }
#pragma unroll
            for (int nf = 0; nf < 8; nf++)
#pragma unroll
                for (int mf = 0; mf < 2; mf++) mma_bf16(acc[mf][nf], fah[mf], fbh[nf]);
#pragma unroll
            for (int nf = 0; nf < 8; nf++)
#pragma unroll
                for (int mf = 0; mf < 2; mf++) mma_bf16(acc[mf][nf], fah[mf], fbl[nf]);
#pragma unroll
            for (int nf = 0; nf < 8; nf++)
#pragma unroll
                for (int mf = 0; mf < 2; mf++) mma_bf16(acc[mf][nf], fal[mf], fbh[nf]);
        }
    };

    const int nk = KK >> 5;
    load_stage(0, 0);
    asm volatile("cp.async.commit_group;");
    for (int kt = 0; kt < nk; kt++) {
        if (kt + 1 < nk) {
            load_stage(kt + 1, (kt + 1) & 1);
            asm volatile("cp.async.commit_group;");
            asm volatile("cp.async.wait_group 1;");
        } else {
            asm volatile("cp.async.wait_group 0;");
        }
        __syncthreads();
        mma_stage(kt & 1);
        __syncthreads();
    }

    const int gr = lane >> 2, cp = (lane & 3) * 2;
#pragma unroll
    for (int mf = 0; mf < 2; mf++) {
#pragma unroll
        for (int nf = 0; nf < 8; nf++) {
            const int oc = oc0 + n0 + nf * 8 + cp;
            const int hh = oc >> 6, d = oc & 63;
            const float b0 = bias[oc], b1 = bias[oc + 1];
#pragma unroll
            for (int half = 0; half < 2; half++) {
                const int s = sl0 + m0 + mf * 16 + gr + half * 8;
                bf16 h0, l0, h1, l1;
                split2(acc[mf][nf][half * 2 + 0] + b0, h0, l0);
                split2(acc[mf][nf][half * 2 + 1] + b1, h1, l1);
                if (seg < 2) {
                    bf16* Dh = (seg == 0) ? g_qh : g_kh;
                    bf16* Dl = (seg == 0) ? g_ql : g_kl;
                    const size_t idx = (((size_t)((b * NH + hh) * SEQ + s)) << 6) + d;
                    *(__nv_bfloat162*)(Dh + idx) = __nv_bfloat162(h0, h1);
                    *(__nv_bfloat162*)(Dl + idx) = __nv_bfloat162(l0, l1);
                } else {
                    const size_t base = ((size_t)((b * NH + hh) * 64 + d)) * SEQ + s;
                    g_vth[base] = h0; g_vtl[base] = l0;
                    g_vth[base + SEQ] = h1; g_vtl[base + SEQ] = l1;
                }
            }
        }
    }
}

// ---------------------------------------------------------------------------
// Fused attention for ONE head pair hp. blockIdx.y selects (b, h within pair).
// Phase A: exact rowsums of exp(S/8) (smem handoff). Phase B: recompute S,
// normalize, write final P once (streaming), PV from registers.
// ---------------------------------------------------------------------------
__global__ void __launch_bounds__(256, 2)
attn_fused(int hp, float* __restrict__ attn, float* __restrict__ out)
{
    extern __shared__ bf16 smB[];
    float* s_rs = (float*)(smB + 54272);          // [128] row sums
    const int rt = 15 - blockIdx.x;
    const int b = blockIdx.y >> 1;
    const int hh = 2 * hp + (blockIdx.y & 1);
    const int bh = b * NH + hh;
    const int r0 = rt * 128;
    const int tid = threadIdx.x, lane = tid & 31, w = tid >> 5;
    float* attn_base = attn + (size_t)bh * SEQ * SEQ;

    // upper-triangle zero-fill for these rows (final values, evict-first)
    const int zc = 1920 - r0;
    if (zc > 0) {
        const int zc4 = zc >> 2;
        for (int idx = tid; idx < 128 * zc4; idx += 256) {
            const int row = idx / zc4, c = (idx % zc4) * 4;
            stg_cs_z4(attn_base + (size_t)(r0 + row) * SEQ + r0 + 128 + c);
        }
    }

    // stage Q once, extract persistent A-frags
    {
        bf16* Th = smB;
        bf16* Tl = smB + 9216;
#pragma unroll
        for (int i = 0; i < 4; i++) {
            const int idx = i * 256 + tid;
            const int row = idx >> 3, q8 = (idx & 7) * 8;
            const size_t off = ((size_t)bh * SEQ + r0 + row) * 64 + q8;
            *(uint4*)(Th + row * 72 + q8) = *(const uint4*)(g_qh + off);
            *(uint4*)(Tl + row * 72 + q8) = *(const uint4*)(g_ql + off);
        }
    }
    __syncthreads();
    uint32_t qh[4][4], ql[4][4];
    {
        const int ar = lane & 15;
#pragma unroll
        for (int kc = 0; kc < 4; kc++) {
            const int ac = kc * 16 + ((lane >> 4) & 1) * 8;
            ldmA4(qh[kc], smB + (w * 16 + ar) * 72 + ac);
            ldmA4(ql[kc], smB + 9216 + (w * 16 + ar) * 72 + ac);
        }
    }
    __syncthreads();

    const int rlA = w * 16 + (lane >> 2), rlB = rlA + 8;

    auto load_k = [&](int jt, int st) {
        bf16* base = smB + st * 18432;
        const int j0 = jt * 128;
#pragma unroll
        for (int i = 0; i < 4; i++) {
            const int idx = i * 256 + tid;
            const int row = idx >> 3, q8 = (idx & 7) * 8;
            const size_t off = ((size_t)bh * SEQ + j0 + row) * 64 + q8;
            cp_async16(base + row * 72 + q8, g_kh + off);
            cp_async16(base + 9216 + row * 72 + q8, g_kl + off);
        }
    };
    auto load_v = [&](int jt) {
        bf16* Vh = smB + 36864;
        const int j0 = jt * 128;
#pragma unroll
        for (int i = 0; i < 4; i++) {
            const int idx = i * 256 + tid;
            const int d = idx >> 4, q8 = (idx & 15) * 8;
            const size_t off = ((size_t)bh * 64 + d) * SEQ + j0 + q8;
            cp_async16(Vh + d * 136 + q8, g_vth + off);
            cp_async16(Vh + 8704 + d * 136 + q8, g_vtl + off);
        }
    };

    // ================= phase A: rowsums =================
    {
        float rs0 = 0.f, rs1 = 0.f;
        load_k(0, 0);
        asm volatile("cp.async.commit_group;");
        for (int jt = 0; jt <= rt; jt++) {
            if (jt < rt) {
                load_k(jt + 1, (jt + 1) & 1);
                asm volatile("cp.async.commit_group;");
                asm volatile("cp.async.wait_group 1;");
            } else {
                asm volatile("cp.async.wait_group 0;");
            }
            __syncthreads();
            bf16* Kh = smB + (jt & 1) * 18432;
            const bool diag = (jt == rt);

#pragma unroll
            for (int nc = 0; nc < 4; nc++) {
                float S[4][4];
#pragma unroll
                for (int i = 0; i < 4; i++)
#pragma unroll
                    for (int c = 0; c < 4; c++) S[i][c] = 0.f;
#pragma unroll
                for (int kc = 0; kc < 4; kc++) {
                    uint32_t fbh[4][2], fbl[4][2];
#pragma unroll
                    for (int nf = 0; nf < 4; nf += 2) {
                        const bf16* pb = b4addr(Kh, nc * 32 + nf * 8, kc * 16, lane, 72);
                        ldmB4(&fbh[nf][0], pb);
                        ldmB4(&fbl[nf][0], pb + 9216);
                    }
#pragma unroll
                    for (int nf = 0; nf < 4; nf++) mma_bf16(S[nf], qh[kc], fbh[nf]);
#pragma unroll
                    for (int nf = 0; nf < 4; nf++) mma_bf16(S[nf], qh[kc], fbl[nf]);
#pragma unroll
                    for (int nf = 0; nf < 4; nf++) mma_bf16(S[nf], ql[kc], fbh[nf]);
                }
#pragma unroll
                for (int nf = 0; nf < 4; nf++) {
                    const int jl = nc * 32 + nf * 8 + (lane & 3) * 2;
                    float p0 = __expf(S[nf][0] * 0.125f);
                    float p1 = __expf(S[nf][1] * 0.125f);
                    float p2 = __expf(S[nf][2] * 0.125f);
                    float p3 = __expf(S[nf][3] * 0.125f);
                    if (diag) {
                        if (jl > rlA)     p0 = 0.f;
                        if (jl + 1 > rlA) p1 = 0.f;
                        if (jl > rlB)     p2 = 0.f;
                        if (jl + 1 > rlB) p3 = 0.f;
                    }
                    rs0 += p0 + p1;
                    rs1 += p2 + p3;
                }
            }
            __syncthreads();
        }
        rs0 += __shfl_xor_sync(~0u, rs0, 1); rs0 += __shfl_xor_sync(~0u, rs0, 2);
        rs1 += __shfl_xor_sync(~0u, rs1, 1); rs1 += __shfl_xor_sync(~0u, rs1, 2);
        if ((lane & 3) == 0) {
            s_rs[rlA] = rs0;
            s_rs[rlB] = rs1;
        }
        __syncthreads();
    }

    const float inv0 = 1.f / s_rs[rlA];
    const float inv1 = 1.f / s_rs[rlB];

    // ================= phase B: P write + PV =================
    float O[8][4];
#pragma unroll
    for (int i = 0; i < 8; i++)
#pragma unroll
        for (int c = 0; c < 4; c++) O[i][c] = 0.f;

    load_k(0, 0);
    asm volatile("cp.async.commit_group;");
    for (int jt = 0; jt <= rt; jt++) {
        load_v(jt);
        asm volatile("cp.async.commit_group;");
        if (jt < rt) {
            load_k(jt + 1, (jt + 1) & 1);
            asm volatile("cp.async.commit_group;");
            asm volatile("cp.async.wait_group 2;");
        } else {
            asm volatile("cp.async.wait_group 1;");
        }
        __syncthreads();
        bf16* Kh = smB + (jt & 1) * 18432;
        bf16* Vh = smB + 36864;
        const int j0 = jt * 128;
        const bool diag = (jt == rt);

#pragma unroll
        for (int nc = 0; nc < 4; nc++) {
            float S[4][4];
#pragma unroll
            for (int i = 0; i < 4; i++)
#pragma unroll
                for (int c = 0; c < 4; c++) S[i][c] = 0.f;
#pragma unroll
            for (int kc = 0; kc < 4; kc++) {
                uint32_t kbh[4][2], kbl[4][2];
#pragma unroll
                for (int nf = 0; nf < 4; nf += 2) {
                    const bf16* pb = b4addr(Kh, nc * 32 + nf * 8, kc * 16, lane, 72);
                    ldmB4(&kbh[nf][0], pb);
                    ldmB4(&kbl[nf][0], pb + 9216);
                }
#pragma unroll
                for (int nf = 0; nf < 4; nf++) mma_bf16(S[nf], qh[kc], kbh[nf]);
#pragma unroll
                for (int nf = 0; nf < 4; nf++) mma_bf16(S[nf], qh[kc], kbl[nf]);
#pragma unroll
                for (int nf = 0; nf < 4; nf++) mma_bf16(S[nf], ql[kc], kbh[nf]);
            }

            uint32_t pah[2][4], pal[2][4];
#pragma unroll
            for (int nf = 0; nf < 4; nf++) {
                const int jl = nc * 32 + nf * 8 + (lane & 3) * 2;
                float p0 = __expf(S[nf][0] * 0.125f);
                float p1 = __expf(S[nf][1] * 0.125f);
                float p2 = __expf(S[nf][2] * 0.125f);
                float p3 = __expf(S[nf][3] * 0.125f);
                if (diag) {
                    if (jl > rlA)     p0 = 0.f;
                    if (jl + 1 > rlA) p1 = 0.f;
                    if (jl > rlB)     p2 = 0.f;
                    if (jl + 1 > rlB) p3 = 0.f;
                }
                p0 *= inv0; p1 *= inv0; p2 *= inv1; p3 *= inv1;
                stg_cs_f2(attn_base + (size_t)(r0 + rlA) * SEQ + j0 + jl, p0, p1);
                stg_cs_f2(attn_base + (size_t)(r0 + rlB) * SEQ + j0 + jl, p2, p3);

                bf16 h0,l0,h1,l1,h2,l2,h3,l3;
                split2(p0, h0, l0); split2(p1, h1, l1);
                split2(p2, h2, l2); split2(p3, h3, l3);
                const int f = nf >> 1, sl = (nf & 1) * 2;
                pah[f][sl + 0] = packbf(h0, h1);
                pah[f][sl + 1] = packbf(h2, h3);
                pal[f][sl + 0] = packbf(l0, l1);
                pal[f][sl + 1] = packbf(l2, l3);
            }

            if (nc == 0) {
                if (jt < rt) asm volatile("cp.async.wait_group 1;");
                else         asm volatile("cp.async.wait_group 0;");
                __syncthreads();
            }

#pragma unroll
            for (int kf = 0; kf < 2; kf++) {
                const int kg = nc * 32 + kf * 16;
                uint32_t vbh[8][2], vbl[8][2];
#pragma unroll
                for (int nf = 0; nf < 8; nf += 2) {
                    const bf16* pv = b4addr(Vh, nf * 8, kg, lane, 136);
                    ldmB4(&vbh[nf][0], pv);
                    ldmB4(&vbl[nf][0], pv + 8704);
                }
#pragma unroll
                for (int nf = 0; nf < 8; nf++) mma_bf16(O[nf], pah[kf], vbh[nf]);
#pragma unroll
                for (int nf = 0; nf < 8; nf++) mma_bf16(O[nf], pah[kf], vbl[nf]);
#pragma unroll
                for (int nf = 0; nf < 8; nf++) mma_bf16(O[nf], pal[kf], vbh[nf]);
            }
        }
        __syncthreads();
    }

#pragma unroll
    for (int nf = 0; nf < 8; nf++) {
        const int d = nf * 8 + (lane & 3) * 2;
        const int s0 = r0 + rlA, s1 = r0 + rlB;
        float2 o0; o0.x = O[nf][0]; o0.y = O[nf][1];
        float2 o1; o1.x = O[nf][2]; o1.y = O[nf][3];
        *(float2*)(out + (((size_t)(b * SEQ + s0)) * NH + hh) * 64 + d) = o0;
        *(float2*)(out + (((size_t)(b * SEQ + s1)) * NH + hh) * 64 + d) = o1;
    }
}

extern "C" void kernel_launch(void* const* d_in, const int* in_sizes, int n_in,
                              void* d_out, int out_size)
{
    const float* x  = (const float*)d_in[0];
    const float* wq = (const float*)d_in[2];
    const float* bq = (const float*)d_in[3];
    const float* wk = (const float*)d_in[4];
    const float* bk = (const float*)d_in[5];
    const float* wv = (const float*)d_in[6];
    const float* bv = (const float*)d_in[7];

    float* out  = (float*)d_out;
    float* attn = out + (size_t)Bsz * SEQ * NH * 64;

    // side stream + events (created per call, never destroyed — graph-safe)
    cudaStream_t s1;
    cudaEvent_t evQ[4], eEnd;
    cudaStreamCreateWithFlags(&s1, cudaStreamNonBlocking);
    for (int i = 0; i < 4; i++) cudaEventCreateWithFlags(&evQ[i], cudaEventDisableTiming);
    cudaEventCreateWithFlags(&eEnd, cudaEventDisableTiming);

    cudaFuncSetAttribute(qkv_gemm, cudaFuncAttributeMaxDynamicSharedMemorySize, 81920);
    cudaFuncSetAttribute(attn_fused, cudaFuncAttributeMaxDynamicSharedMemorySize, 109056);

    const int prep_items = Bsz*SEQ*CH + CH*1536;
    prep_kernel<<<(prep_items + 255) / 256, 256>>>(x, wq, wk, wv);

    // qkv head-pair chunks on stream 0, events after each
    for (int hp = 0; hp < 4; hp++) {
        qkv_gemm<<<dim3(64, 3), 256, 81920>>>(hp, bq, bk, bv);
        cudaEventRecord(evQ[hp], 0);
    }
    // attention chunks on stream 1, each gated on its head pair's qkv
    for (int hp = 0; hp < 4; hp++) {
        cudaStreamWaitEvent(s1, evQ[hp], 0);
        attn_fused<<<dim3(16, 8), 256, 109056, s1>>>(hp, attn, out);
    }
    // join back to origin stream
    cudaEventRecord(eEnd, s1);
    cudaStreamWaitEvent(0, eEnd, 0);
}

// round 16
// speedup vs baseline: 1.4145x; 1.4145x over previous
#include <cuda_runtime.h>
#include <cuda_bf16.h>
#include <cstdint>

#define Bsz 4
#define SEQ 2048
#define CH  512
#define NH  8

typedef __nv_bfloat16 bf16;

__device__ bf16 g_xh[Bsz*SEQ*CH], g_xl[Bsz*SEQ*CH];
__device__ bf16 g_wqh[CH*3*CH], g_wql[CH*3*CH];        // [oc][kg=t*512+c]
__device__ bf16 g_wkh[CH*3*CH], g_wkl[CH*3*CH];
__device__ bf16 g_wvh[CH*CH],   g_wvl[CH*CH];          // [oc][c]
__device__ bf16 g_qh[Bsz*NH*SEQ*64], g_ql[Bsz*NH*SEQ*64];   // [b,h,s,d]
__device__ bf16 g_kh[Bsz*NH*SEQ*64], g_kl[Bsz*NH*SEQ*64];   // [b,h,s,d]
__device__ bf16 g_vth[Bsz*NH*64*SEQ], g_vtl[Bsz*NH*64*SEQ]; // [b,h,d,s]

__device__ __forceinline__ void split2(float x, bf16& h, bf16& l) {
    h = __float2bfloat16(x);
    l = __float2bfloat16(x - __bfloat162float(h));
}
__device__ __forceinline__ uint32_t packbf(bf16 a, bf16 b) {
    __nv_bfloat162 t(a, b);
    return *(uint32_t*)&t;
}
__device__ __forceinline__ void ldmA4(uint32_t* a, const bf16* p) {
    uint32_t addr = (uint32_t)__cvta_generic_to_shared(p);
    asm volatile("ldmatrix.sync.aligned.m8n8.x4.shared.b16 {%0,%1,%2,%3}, [%4];"
        : "=r"(a[0]), "=r"(a[1]), "=r"(a[2]), "=r"(a[3]) : "r"(addr));
}
__device__ __forceinline__ void ldmB4(uint32_t* b, const bf16* p) {
    uint32_t addr = (uint32_t)__cvta_generic_to_shared(p);
    asm volatile("ldmatrix.sync.aligned.m8n8.x4.shared.b16 {%0,%1,%2,%3}, [%4];"
        : "=r"(b[0]), "=r"(b[1]), "=r"(b[2]), "=r"(b[3]) : "r"(addr));
}
__device__ __forceinline__ void mma_bf16(float* d, const uint32_t* a, const uint32_t* b) {
    asm volatile("mma.sync.aligned.m16n8k16.row.col.f32.bf16.bf16.f32 "
        "{%0,%1,%2,%3}, {%4,%5,%6,%7}, {%8,%9}, {%0,%1,%2,%3};"
        : "+f"(d[0]), "+f"(d[1]), "+f"(d[2]), "+f"(d[3])
        : "r"(a[0]), "r"(a[1]), "r"(a[2]), "r"(a[3]), "r"(b[0]), "r"(b[1]));
}
__device__ __forceinline__ void cp_async16(void* smem, const void* gmem) {
    uint32_t s = (uint32_t)__cvta_generic_to_shared(smem);
    asm volatile("cp.async.cg.shared.global [%0], [%1], 16;" :: "r"(s), "l"(gmem));
}
__device__ __forceinline__ const bf16* b4addr(const bf16* base, int n0, int kk,
                                              int lane, int str) {
    return base + (size_t)(n0 + (lane & 7) + ((lane >> 4) << 3)) * str
                + kk + ((lane >> 3) & 1) * 8;
}
__device__ __forceinline__ void stg_cs_f2(float* p, float x, float y) {
    asm volatile("st.global.cs.v2.f32 [%0], {%1,%2};" :: "l"(p), "f"(x), "f"(y) : "memory");
}
__device__ __forceinline__ void stg_cs_z4(float* p) {
    asm volatile("st.global.cs.v4.b32 [%0], {%1,%1,%1,%1};" :: "l"(p), "r"(0u) : "memory");
}

// ---------------------------------------------------------------------------
// Prep: split x into bf16 hi/lo AND repack+split the weights — one launch.
// ---------------------------------------------------------------------------
__global__ void prep_kernel(const float* __restrict__ x,
                            const float* __restrict__ wq,
                            const float* __restrict__ wk,
                            const float* __restrict__ wv)
{
    int i = blockIdx.x * 256 + threadIdx.x;
    const int NX = Bsz * SEQ * CH;
    if (i < NX) {
        split2(x[i], g_xh[i], g_xl[i]);
        return;
    }
    i -= NX;
    if (i >= CH * 1536) return;
    const int oc = i / 1536, kg = i % 1536;
    const int c = kg & 511, t = kg >> 9;
    split2(wq[oc*1536 + c*3 + t], g_wqh[i], g_wql[i]);
    split2(wk[oc*1536 + c*3 + t], g_wkh[i], g_wkl[i]);
    if (kg < CH) split2(wv[oc*CH + kg], g_wvh[oc*CH + kg], g_wvl[oc*CH + kg]);
}

// ---------------------------------------------------------------------------
// QKV GEMM. Block 128x128, Kc=32, 256 threads (8 warps, 32x64 warp tiles),
// cp.async double-buffered, x4 B-ldmatrix. bf16x3 split accum in fp32.
// ---------------------------------------------------------------------------
__global__ void __launch_bounds__(256)
qkv_gemm(const float* __restrict__ bq, const float* __restrict__ bk,
         const float* __restrict__ bv)
{
    extern __shared__ bf16 sm[];
    const int mt = blockIdx.x, nt = blockIdx.y;
    const int seg = nt >> 2;
    const int oc0 = (nt & 3) * 128;
    const int gm0 = mt * 128;
    const int b = gm0 >> 11, sl0 = gm0 & 2047;
    const int KK = (seg < 2) ? 1536 : 512;
    const bf16* Wh = (seg == 0) ? g_wqh : (seg == 1) ? g_wkh : g_wvh;
    const bf16* Wl = (seg == 0) ? g_wql : (seg == 1) ? g_wkl : g_wvl;
    const float* bias = (seg == 0) ? bq : (seg == 1) ? bk : bv;

    const int tid = threadIdx.x, lane = tid & 31, wid = tid >> 5;
    const int m0 = (wid >> 1) * 32, n0 = (wid & 1) * 64;

    float acc[2][8][4];
#pragma unroll
    for (int i = 0; i < 2; i++)
#pragma unroll
        for (int j = 0; j < 8; j++)
#pragma unroll
            for (int c = 0; c < 4; c++) acc[i][j][c] = 0.f;

    auto load_stage = [&](int kt, int st) {
        bf16* Ah = sm + st * 20480;
        bf16* Al = Ah + 5120;
        bf16* Bh = Ah + 10240;
        bf16* Bl = Ah + 15360;
        const int k0 = kt * 32;
#pragma unroll
        for (int i = 0; i < 2; i++) {
            const int idx = tid + i * 256;
            const int row = idx >> 2, q8 = (idx & 3) * 8;
            int srow, c;
            if (seg < 2) { c = (k0 & 511) + q8; srow = sl0 + row + (k0 >> 9) - 2; }
            else         { c = k0 + q8;         srow = sl0 + row; }
            if (srow >= 0) {
                const size_t off = (((size_t)(b * SEQ + srow)) << 9) + c;
                cp_async16(Ah + row * 40 + q8, g_xh + off);
                cp_async16(Al + row * 40 + q8, g_xl + off);
            } else {
                const uint4 z = make_uint4(0,0,0,0);
                *(uint4*)(Ah + row * 40 + q8) = z;
                *(uint4*)(Al + row * 40 + q8) = z;
            }
            const size_t woff = (size_t)(oc0 + row) * KK + k0 + q8;
            cp_async16(Bh + row * 40 + q8, Wh + woff);
            cp_async16(Bl + row * 40 + q8, Wl + woff);
        }
    };

    auto mma_stage = [&](int st) {
        bf16* Ah = sm + st * 20480;
        bf16* Al = Ah + 5120;
        bf16* Bh = Ah + 10240;
#pragma unroll
        for (int kk = 0; kk < 32; kk += 16) {
            uint32_t fah[2][4], fal[2][4], fbh[8][2], fbl[8][2];
            const int ar = lane & 15, ac = kk + ((lane >> 4) & 1) * 8;
#pragma unroll
            for (int mf = 0; mf < 2; mf++) {
                ldmA4(fah[mf], Ah + (m0 + mf * 16 + ar) * 40 + ac);
                ldmA4(fal[mf], Al + (m0 + mf * 16 + ar) * 40 + ac);
            }
#pragma unroll
            for (int nf = 0; nf < 8; nf += 2) {
                const bf16* pb = b4addr(Bh, n0 + nf * 8, kk, lane, 40);
                ldmB4(&fbh[nf][0], pb);
                ldmB4(&fbl[nf][0], pb + 5120);
            }
#pragma unroll
            for (int nf = 0; nf < 8; nf++)
#pragma unroll
                for (int mf = 0; mf < 2; mf++) mma_bf16(acc[mf][nf], fah[mf], fbh[nf]);
#pragma unroll
            for (int nf = 0; nf < 8; nf++)
#pragma unroll
                for (int mf = 0; mf < 2; mf++) mma_bf16(acc[mf][nf], fah[mf], fbl[nf]);
#pragma unroll
            for (int nf = 0; nf < 8; nf++)
#pragma unroll
                for (int mf = 0; mf < 2; mf++) mma_bf16(acc[mf][nf], fal[mf], fbh[nf]);
        }
    };

    const int nk = KK >> 5;
    load_stage(0, 0);
    asm volatile("cp.async.commit_group;");
    for (int kt = 0; kt < nk; kt++) {
        if (kt + 1 < nk) {
            load_stage(kt + 1, (kt + 1) & 1);
            asm volatile("cp.async.commit_group;");
            asm volatile("cp.async.wait_group 1;");
        } else {
            asm volatile("cp.async.wait_group 0;");
        }
        __syncthreads();
        mma_stage(kt & 1);
        __syncthreads();
    }

    const int gr = lane >> 2, cp = (lane & 3) * 2;
#pragma unroll
    for (int mf = 0; mf < 2; mf++) {
#pragma unroll
        for (int nf = 0; nf < 8; nf++) {
            const int oc = oc0 + n0 + nf * 8 + cp;
            const int hh = oc >> 6, d = oc & 63;
            const float b0 = bias[oc], b1 = bias[oc + 1];
#pragma unroll
            for (int half = 0; half < 2; half++) {
                const int s = sl0 + m0 + mf * 16 + gr + half * 8;
                bf16 h0, l0, h1, l1;
                split2(acc[mf][nf][half * 2 + 0] + b0, h0, l0);
                split2(acc[mf][nf][half * 2 + 1] + b1, h1, l1);
                if (seg < 2) {
                    bf16* Dh = (seg == 0) ? g_qh : g_kh;
                    bf16* Dl = (seg == 0) ? g_ql : g_kl;
                    const size_t idx = (((size_t)((b * NH + hh) * SEQ + s)) << 6) + d;
                    *(__nv_bfloat162*)(Dh + idx) = __nv_bfloat162(h0, h1);
                    *(__nv_bfloat162*)(Dl + idx) = __nv_bfloat162(l0, l1);
                } else {
                    const size_t base = ((size_t)((b * NH + hh) * 64 + d)) * SEQ + s;
                    g_vth[base] = h0; g_vtl[base] = l0;
                    g_vth[base + SEQ] = h1; g_vtl[base + SEQ] = l1;
                }
            }
        }
    }
}

// ---------------------------------------------------------------------------
// Fused attention: phase A computes exact rowsums of exp(S/8) (3-pass split),
// passes them through smem; phase B recomputes S, normalizes, writes final P
// once (streaming stores) and accumulates O = P V from registers.
// K double-buffered, V single-buffered. smem = 108544 B K/V + 512 B sums.
// ---------------------------------------------------------------------------
__global__ void __launch_bounds__(256, 2)
attn_fused(float* __restrict__ attn, float* __restrict__ out)
{
    extern __shared__ bf16 smB[];
    float* s_rs = (float*)(smB + 54272);          // [128] row sums
    const int rt = 15 - blockIdx.x;
    const int bh = blockIdx.y;
    const int b = bh >> 3, hh = bh & 7;
    const int r0 = rt * 128;
    const int tid = threadIdx.x, lane = tid & 31, w = tid >> 5;
    float* attn_base = attn + (size_t)bh * SEQ * SEQ;

    // upper-triangle zero-fill for these rows (final values, evict-first)
    const int zc = 1920 - r0;
    if (zc > 0) {
        const int zc4 = zc >> 2;
        for (int idx = tid; idx < 128 * zc4; idx += 256) {
            const int row = idx / zc4, c = (idx % zc4) * 4;
            stg_cs_z4(attn_base + (size_t)(r0 + row) * SEQ + r0 + 128 + c);
        }
    }

    // stage Q once, extract persistent A-frags
    {
        bf16* Th = smB;
        bf16* Tl = smB + 9216;
#pragma unroll
        for (int i = 0; i < 4; i++) {
            const int idx = i * 256 + tid;
            const int row = idx >> 3, q8 = (idx & 7) * 8;
            const size_t off = ((size_t)bh * SEQ + r0 + row) * 64 + q8;
            *(uint4*)(Th + row * 72 + q8) = *(const uint4*)(g_qh + off);
            *(uint4*)(Tl + row * 72 + q8) = *(const uint4*)(g_ql + off);
        }
    }
    __syncthreads();
    uint32_t qh[4][4], ql[4][4];
    {
        const int ar = lane & 15;
#pragma unroll
        for (int kc = 0; kc < 4; kc++) {
            const int ac = kc * 16 + ((lane >> 4) & 1) * 8;
            ldmA4(qh[kc], smB + (w * 16 + ar) * 72 + ac);
            ldmA4(ql[kc], smB + 9216 + (w * 16 + ar) * 72 + ac);
        }
    }
    __syncthreads();

    const int rlA = w * 16 + (lane >> 2), rlB = rlA + 8;

    auto load_k = [&](int jt, int st) {
        bf16* base = smB + st * 18432;
        const int j0 = jt * 128;
#pragma unroll
        for (int i = 0; i < 4; i++) {
            const int idx = i * 256 + tid;
            const int row = idx >> 3, q8 = (idx & 7) * 8;
            const size_t off = ((size_t)bh * SEQ + j0 + row) * 64 + q8;
            cp_async16(base + row * 72 + q8, g_kh + off);
            cp_async16(base + 9216 + row * 72 + q8, g_kl + off);
        }
    };
    auto load_v = [&](int jt) {
        bf16* Vh = smB + 36864;
        const int j0 = jt * 128;
#pragma unroll
        for (int i = 0; i < 4; i++) {
            const int idx = i * 256 + tid;
            const int d = idx >> 4, q8 = (idx & 15) * 8;
            const size_t off = ((size_t)bh * 64 + d) * SEQ + j0 + q8;
            cp_async16(Vh + d * 136 + q8, g_vth + off);
            cp_async16(Vh + 8704 + d * 136 + q8, g_vtl + off);
        }
    };

    // ================= phase A: rowsums =================
    {
        float rs0 = 0.f, rs1 = 0.f;
        load_k(0, 0);
        asm volatile("cp.async.commit_group;");
        for (int jt = 0; jt <= rt; jt++) {
            if (jt < rt) {
                load_k(jt + 1, (jt + 1) & 1);
                asm volatile("cp.async.commit_group;");
                asm volatile("cp.async.wait_group 1;");
            } else {
                asm volatile("cp.async.wait_group 0;");
            }
            __syncthreads();
            bf16* Kh = smB + (jt & 1) * 18432;
            const bool diag = (jt == rt);

#pragma unroll
            for (int nc = 0; nc < 4; nc++) {
                float S[4][4];
#pragma unroll
                for (int i = 0; i < 4; i++)
#pragma unroll
                    for (int c = 0; c < 4; c++) S[i][c] = 0.f;
#pragma unroll
                for (int kc = 0; kc < 4; kc++) {
                    uint32_t fbh[4][2], fbl[4][2];
#pragma unroll
                    for (int nf = 0; nf < 4; nf += 2) {
                        const bf16* pb = b4addr(Kh, nc * 32 + nf * 8, kc * 16, lane, 72);
                        ldmB4(&fbh[nf][0], pb);
                        ldmB4(&fbl[nf][0], pb + 9216);
                    }
#pragma unroll
                    for (int nf = 0; nf < 4; nf++) mma_bf16(S[nf], qh[kc], fbh[nf]);
#pragma unroll
                    for (int nf = 0; nf < 4; nf++) mma_bf16(S[nf], qh[kc], fbl[nf]);
#pragma unroll
                    for (int nf = 0; nf < 4; nf++) mma_bf16(S[nf], ql[kc], fbh[nf]);
                }
#pragma unroll
                for (int nf = 0; nf < 4; nf++) {
                    const int jl = nc * 32 + nf * 8 + (lane & 3) * 2;
                    float p0 = __expf(S[nf][0] * 0.125f);
                    float p1 = __expf(S[nf][1] * 0.125f);
                    float p2 = __expf(S[nf][2] * 0.125f);
                    float p3 = __expf(S[nf][3] * 0.125f);
                    if (diag) {
                        if (jl > rlA)     p0 = 0.f;
                        if (jl + 1 > rlA) p1 = 0.f;
                        if (jl > rlB)     p2 = 0.f;
                        if (jl + 1 > rlB) p3 = 0.f;
                    }
                    rs0 += p0 + p1;
                    rs1 += p2 + p3;
                }
            }
            __syncthreads();
        }
        rs0 += __shfl_xor_sync(~0u, rs0, 1); rs0 += __shfl_xor_sync(~0u, rs0, 2);
        rs1 += __shfl_xor_sync(~0u, rs1, 1); rs1 += __shfl_xor_sync(~0u, rs1, 2);
        if ((lane & 3) == 0) {
            s_rs[rlA] = rs0;
            s_rs[rlB] = rs1;
        }
        __syncthreads();
    }

    const float inv0 = 1.f / s_rs[rlA];
    const float inv1 = 1.f / s_rs[rlB];

    // ================= phase B: P write + PV =================
    float O[8][4];
#pragma unroll
    for (int i = 0; i < 8; i++)
#pragma unroll
        for (int c = 0; c < 4; c++) O[i][c] = 0.f;

    load_k(0, 0);
    asm volatile("cp.async.commit_group;");
    for (int jt = 0; jt <= rt; jt++) {
        load_v(jt);
        asm volatile("cp.async.commit_group;");
        if (jt < rt) {
            load_k(jt + 1, (jt + 1) & 1);
            asm volatile("cp.async.commit_group;");
            asm volatile("cp.async.wait_group 2;");
        } else {
            asm volatile("cp.async.wait_group 1;");
        }
        __syncthreads();
        bf16* Kh = smB + (jt & 1) * 18432;
        bf16* Vh = smB + 36864;
        const int j0 = jt * 128;
        const bool diag = (jt == rt);

#pragma unroll
        for (int nc = 0; nc < 4; nc++) {
            float S[4][4];
#pragma unroll
            for (int i = 0; i < 4; i++)
#pragma unroll
                for (int c = 0; c < 4; c++) S[i][c] = 0.f;
#pragma unroll
            for (int kc = 0; kc < 4; kc++) {
                uint32_t kbh[4][2], kbl[4][2];
#pragma unroll
                for (int nf = 0; nf < 4; nf += 2) {
                    const bf16* pb = b4addr(Kh, nc * 32 + nf * 8, kc * 16, lane, 72);
                    ldmB4(&kbh[nf][0], pb);
                    ldmB4(&kbl[nf][0], pb + 9216);
                }
#pragma unroll
                for (int nf = 0; nf < 4; nf++) mma_bf16(S[nf], qh[kc], kbh[nf]);
#pragma unroll
                for (int nf = 0; nf < 4; nf++) mma_bf16(S[nf], qh[kc], kbl[nf]);
#pragma unroll
                for (int nf = 0; nf < 4; nf++) mma_bf16(S[nf], ql[kc], kbh[nf]);
            }

            uint32_t pah[2][4], pal[2][4];
#pragma unroll
            for (int nf = 0; nf < 4; nf++) {
                const int jl = nc * 32 + nf * 8 + (lane & 3) * 2;
                float p0 = __expf(S[nf][0] * 0.125f);
                float p1 = __expf(S[nf][1] * 0.125f);
                float p2 = __expf(S[nf][2] * 0.125f);
                float p3 = __expf(S[nf][3] * 0.125f);
                if (diag) {
                    if (jl > rlA)     p0 = 0.f;
                    if (jl + 1 > rlA) p1 = 0.f;
                    if (jl > rlB)     p2 = 0.f;
                    if (jl + 1 > rlB) p3 = 0.f;
                }
                p0 *= inv0; p1 *= inv0; p2 *= inv1; p3 *= inv1;
                stg_cs_f2(attn_base + (size_t)(r0 + rlA) * SEQ + j0 + jl, p0, p1);
                stg_cs_f2(attn_base + (size_t)(r0 + rlB) * SEQ + j0 + jl, p2, p3);

                bf16 h0,l0,h1,l1,h2,l2,h3,l3;
                split2(p0, h0, l0); split2(p1, h1, l1);
                split2(p2, h2, l2); split2(p3, h3, l3);
                const int f = nf >> 1, sl = (nf & 1) * 2;
                pah[f][sl + 0] = packbf(h0, h1);
                pah[f][sl + 1] = packbf(h2, h3);
                pal[f][sl + 0] = packbf(l0, l1);
                pal[f][sl + 1] = packbf(l2, l3);
            }

            if (nc == 0) {
                if (jt < rt) asm volatile("cp.async.wait_group 1;");
                else         asm volatile("cp.async.wait_group 0;");
                __syncthreads();
            }

#pragma unroll
            for (int kf = 0; kf < 2; kf++) {
                const int kg = nc * 32 + kf * 16;
                uint32_t vbh[8][2], vbl[8][2];
#pragma unroll
                for (int nf = 0; nf < 8; nf += 2) {
                    const bf16* pv = b4addr(Vh, nf * 8, kg, lane, 136);
                    ldmB4(&vbh[nf][0], pv);
                    ldmB4(&vbl[nf][0], pv + 8704);
                }
#pragma unroll
                for (int nf = 0; nf < 8; nf++) mma_bf16(O[nf], pah[kf], vbh[nf]);
#pragma unroll
                for (int nf = 0; nf < 8; nf++) mma_bf16(O[nf], pah[kf], vbl[nf]);
#pragma unroll
                for (int nf = 0; nf < 8; nf++) mma_bf16(O[nf], pal[kf], vbh[nf]);
            }
        }
        __syncthreads();
    }

#pragma unroll
    for (int nf = 0; nf < 8; nf++) {
        const int d = nf * 8 + (lane & 3) * 2;
        const int s0 = r0 + rlA, s1 = r0 + rlB;
        float2 o0; o0.x = O[nf][0]; o0.y = O[nf][1];
        float2 o1; o1.x = O[nf][2]; o1.y = O[nf][3];
        *(float2*)(out + (((size_t)(b * SEQ + s0)) * NH + hh) * 64 + d) = o0;
        *(float2*)(out + (((size_t)(b * SEQ + s1)) * NH + hh) * 64 + d) = o1;
    }
}

extern "C" void kernel_launch(void* const* d_in, const int* in_sizes, int n_in,
                              void* d_out, int out_size)
{
    const float* x  = (const float*)d_in[0];
    const float* wq = (const float*)d_in[2];
    const float* bq = (const float*)d_in[3];
    const float* wk = (const float*)d_in[4];
    const float* bk = (const float*)d_in[5];
    const float* wv = (const float*)d_in[6];
    const float* bv = (const float*)d_in[7];

    float* out  = (float*)d_out;
    float* attn = out + (size_t)Bsz * SEQ * NH * 64;

    const int prep_items = Bsz*SEQ*CH + CH*1536;
    prep_kernel<<<(prep_items + 255) / 256, 256>>>(x, wq, wk, wv);

    cudaFuncSetAttribute(qkv_gemm, cudaFuncAttributeMaxDynamicSharedMemorySize, 81920);
    qkv_gemm<<<dim3(64, 12), 256, 81920>>>(bq, bk, bv);

    cudaFuncSetAttribute(attn_fused, cudaFuncAttributeMaxDynamicSharedMemorySize, 109056);
    attn_fused<<<dim3(16, 32), 256, 109056>>>(attn, out);
}

// round 17
// speedup vs baseline: 1.4218x; 1.0052x over previous
#include <cuda_runtime.h>
#include <cuda_bf16.h>
#include <cstdint>

#define Bsz 4
#define SEQ 2048
#define CH  512
#define NH  8

typedef __nv_bfloat16 bf16;

__device__ bf16 g_xh[Bsz*SEQ*CH], g_xl[Bsz*SEQ*CH];
__device__ bf16 g_wqh[CH*3*CH], g_wql[CH*3*CH];        // [oc][kg=t*512+c]
__device__ bf16 g_wkh[CH*3*CH], g_wkl[CH*3*CH];
__device__ bf16 g_wvh[CH*CH],   g_wvl[CH*CH];          // [oc][c]
__device__ bf16 g_qh[Bsz*NH*SEQ*64], g_ql[Bsz*NH*SEQ*64];   // [b,h,s,d]
__device__ bf16 g_kh[Bsz*NH*SEQ*64], g_kl[Bsz*NH*SEQ*64];   // [b,h,s,d]
__device__ bf16 g_vth[Bsz*NH*64*SEQ], g_vtl[Bsz*NH*64*SEQ]; // [b,h,d,s]

__device__ __forceinline__ void split2(float x, bf16& h, bf16& l) {
    h = __float2bfloat16(x);
    l = __float2bfloat16(x - __bfloat162float(h));
}
__device__ __forceinline__ uint32_t packbf(bf16 a, bf16 b) {
    __nv_bfloat162 t(a, b);
    return *(uint32_t*)&t;
}
__device__ __forceinline__ void ldmA4(uint32_t* a, const bf16* p) {
    uint32_t addr = (uint32_t)__cvta_generic_to_shared(p);
    asm volatile("ldmatrix.sync.aligned.m8n8.x4.shared.b16 {%0,%1,%2,%3}, [%4];"
        : "=r"(a[0]), "=r"(a[1]), "=r"(a[2]), "=r"(a[3]) : "r"(addr));
}
__device__ __forceinline__ void ldmB4(uint32_t* b, const bf16* p) {
    uint32_t addr = (uint32_t)__cvta_generic_to_shared(p);
    asm volatile("ldmatrix.sync.aligned.m8n8.x4.shared.b16 {%0,%1,%2,%3}, [%4];"
        : "=r"(b[0]), "=r"(b[1]), "=r"(b[2]), "=r"(b[3]) : "r"(addr));
}
__device__ __forceinline__ void mma_bf16(float* d, const uint32_t* a, const uint32_t* b) {
    asm volatile("mma.sync.aligned.m16n8k16.row.col.f32.bf16.bf16.f32 "
        "{%0,%1,%2,%3}, {%4,%5,%6,%7}, {%8,%9}, {%0,%1,%2,%3};"
        : "+f"(d[0]), "+f"(d[1]), "+f"(d[2]), "+f"(d[3])
        : "r"(a[0]), "r"(a[1]), "r"(a[2]), "r"(a[3]), "r"(b[0]), "r"(b[1]));
}
__device__ __forceinline__ void cp_async16(void* smem, const void* gmem) {
    uint32_t s = (uint32_t)__cvta_generic_to_shared(smem);
    asm volatile("cp.async.cg.shared.global [%0], [%1], 16;" :: "r"(s), "l"(gmem));
}
__device__ __forceinline__ const bf16* b4addr(const bf16* base, int n0, int kk,
                                              int lane, int str) {
    return base + (size_t)(n0 + (lane & 7) + ((lane >> 4) << 3)) * str
                + kk + ((lane >> 3) & 1) * 8;
}
__device__ __forceinline__ void stg_cs_f2(float* p, float x, float y) {
    asm volatile("st.global.cs.v2.f32 [%0], {%1,%2};" :: "l"(p), "f"(x), "f"(y) : "memory");
}
__device__ __forceinline__ void stg_cs_z4(float* p) {
    asm volatile("st.global.cs.v4.b32 [%0], {%1,%1,%1,%1};" :: "l"(p), "r"(0u) : "memory");
}

// ---------------------------------------------------------------------------
// Prep: split x into bf16 hi/lo AND repack+split the weights — one launch.
// ---------------------------------------------------------------------------
__global__ void prep_kernel(const float* __restrict__ x,
                            const float* __restrict__ wq,
                            const float* __restrict__ wk,
                            const float* __restrict__ wv)
{
    int i = blockIdx.x * 256 + threadIdx.x;
    const int NX = Bsz * SEQ * CH;
    if (i < NX) {
        split2(x[i], g_xh[i], g_xl[i]);
        return;
    }
    i -= NX;
    if (i >= CH * 1536) return;
    const int oc = i / 1536, kg = i % 1536;
    const int c = kg & 511, t = kg >> 9;
    split2(wq[oc*1536 + c*3 + t], g_wqh[i], g_wql[i]);
    split2(wk[oc*1536 + c*3 + t], g_wkh[i], g_wkl[i]);
    if (kg < CH) split2(wv[oc*CH + kg], g_wvh[oc*CH + kg], g_wvl[oc*CH + kg]);
}

// ---------------------------------------------------------------------------
// QKV GEMM. Block 128x128, Kc=32, 256 threads (8 warps, 32x64 warp tiles),
// cp.async double-buffered, x4 B-ldmatrix. bf16x3 split accum in fp32.
// ---------------------------------------------------------------------------
__global__ void __launch_bounds__(256, 2)
qkv_gemm(const float* __restrict__ bq, const float* __restrict__ bk,
         const float* __restrict__ bv)
{
    extern __shared__ bf16 sm[];
    const int mt = blockIdx.x, nt = blockIdx.y;
    const int seg = nt >> 2;
    const int oc0 = (nt & 3) * 128;
    const int gm0 = mt * 128;
    const int b = gm0 >> 11, sl0 = gm0 & 2047;
    const int KK = (seg < 2) ? 1536 : 512;
    const bf16* Wh = (seg == 0) ? g_wqh : (seg == 1) ? g_wkh : g_wvh;
    const bf16* Wl = (seg == 0) ? g_wql : (seg == 1) ? g_wkl : g_wvl;
    const float* bias = (seg == 0) ? bq : (seg == 1) ? bk : bv;

    const int tid = threadIdx.x, lane = tid & 31, wid = tid >> 5;
    const int m0 = (wid >> 1) * 32, n0 = (wid & 1) * 64;

    float acc[2][8][4];
#pragma unroll
    for (int i = 0; i < 2; i++)
#pragma unroll
        for (int j = 0; j < 8; j++)
#pragma unroll
            for (int c = 0; c < 4; c++) acc[i][j][c] = 0.f;

    auto load_stage = [&](int kt, int st) {
        bf16* Ah = sm + st * 20480;
        bf16* Al = Ah + 5120;
        bf16* Bh = Ah + 10240;
        bf16* Bl = Ah + 15360;
        const int k0 = kt * 32;
#pragma unroll
        for (int i = 0; i < 2; i++) {
            const int idx = tid + i * 256;
            const int row = idx >> 2, q8 = (idx & 3) * 8;
            int srow, c;
            if (seg < 2) { c = (k0 & 511) + q8; srow = sl0 + row + (k0 >> 9) - 2; }
            else         { c = k0 + q8;         srow = sl0 + row; }
            if (srow >= 0) {
                const size_t off = (((size_t)(b * SEQ + srow)) << 9) + c;
                cp_async16(Ah + row * 40 + q8, g_xh + off);
                cp_async16(Al + row * 40 + q8, g_xl + off);
            } else {
                const uint4 z = make_uint4(0,0,0,0);
                *(uint4*)(Ah + row * 40 + q8) = z;
                *(uint4*)(Al + row * 40 + q8) = z;
            }
            const size_t woff = (size_t)(oc0 + row) * KK + k0 + q8;
            cp_async16(Bh + row * 40 + q8, Wh + woff);
            cp_async16(Bl + row * 40 + q8, Wl + woff);
        }
    };

    auto mma_stage = [&](int st) {
        bf16* Ah = sm + st * 20480;
        bf16* Al = Ah + 5120;
        bf16* Bh = Ah + 10240;
#pragma unroll
        for (int kk = 0; kk < 32; kk += 16) {
            uint32_t fah[2][4], fal[2][4], fbh[8][2], fbl[8][2];
            const int ar = lane & 15, ac = kk + ((lane >> 4) & 1) * 8;
#pragma unroll
            for (int mf = 0; mf < 2; mf++) {
                ldmA4(fah[mf], Ah + (m0 + mf * 16 + ar) * 40 + ac);
                ldmA4(fal[mf], Al + (m0 + mf * 16 + ar) * 40 + ac);
            }
#pragma unroll
            for (int nf = 0; nf < 8; nf += 2) {
                const bf16* pb = b4addr(Bh, n0 + nf * 8, kk, lane, 40);
                ldmB4(&fbh[nf][0], pb);
                ldmB4(&fbl[nf][0], pb + 5120);
            }
#pragma unroll
            for (int nf = 0; nf < 8; nf++)
#pragma unroll
                for (int mf = 0; mf < 2; mf++) mma_bf16(acc[mf][nf], fah[mf], fbh[nf]);
#pragma unroll
            for (int nf = 0; nf < 8; nf++)
#pragma unroll
                for (int mf = 0; mf < 2; mf++) mma_bf16(acc[mf][nf], fah[mf], fbl[nf]);
#pragma unroll
            for (int nf = 0; nf < 8; nf++)
#pragma unroll
                for (int mf = 0; mf < 2; mf++) mma_bf16(acc[mf][nf], fal[mf], fbh[nf]);
        }
    };

    const int nk = KK >> 5;
    load_stage(0, 0);
    asm volatile("cp.async.commit_group;");
    for (int kt = 0; kt < nk; kt++) {
        if (kt + 1 < nk) {
            load_stage(kt + 1, (kt + 1) & 1);
            asm volatile("cp.async.commit_group;");
            asm volatile("cp.async.wait_group 1;");
        } else {
            asm volatile("cp.async.wait_group 0;");
        }
        __syncthreads();
        mma_stage(kt & 1);
        __syncthreads();
    }

    const int gr = lane >> 2, cp = (lane & 3) * 2;
#pragma unroll
    for (int mf = 0; mf < 2; mf++) {
#pragma unroll
        for (int nf = 0; nf < 8; nf++) {
            const int oc = oc0 + n0 + nf * 8 + cp;
            const int hh = oc >> 6, d = oc & 63;
            const float b0 = bias[oc], b1 = bias[oc + 1];
#pragma unroll
            for (int half = 0; half < 2; half++) {
                const int s = sl0 + m0 + mf * 16 + gr + half * 8;
                bf16 h0, l0, h1, l1;
                split2(acc[mf][nf][half * 2 + 0] + b0, h0, l0);
                split2(acc[mf][nf][half * 2 + 1] + b1, h1, l1);
                if (seg < 2) {
                    bf16* Dh = (seg == 0) ? g_qh : g_kh;
                    bf16* Dl = (seg == 0) ? g_ql : g_kl;
                    const size_t idx = (((size_t)((b * NH + hh) * SEQ + s)) << 6) + d;
                    *(__nv_bfloat162*)(Dh + idx) = __nv_bfloat162(h0, h1);
                    *(__nv_bfloat162*)(Dl + idx) = __nv_bfloat162(l0, l1);
                } else {
                    const size_t base = ((size_t)((b * NH + hh) * 64 + d)) * SEQ + s;
                    g_vth[base] = h0; g_vtl[base] = l0;
                    g_vth[base + SEQ] = h1; g_vtl[base + SEQ] = l1;
                }
            }
        }
    }
}

// ---------------------------------------------------------------------------
// Fused attention: phase A computes exact rowsums of exp(S/8) (3-pass split),
// passes them through smem; phase B recomputes S, normalizes, writes final P
// once (streaming stores) and accumulates O = P V from registers.
// K double-buffered, V single-buffered. smem = 108544 B K/V + 512 B sums.
// ---------------------------------------------------------------------------
__global__ void __launch_bounds__(256, 2)
attn_fused(float* __restrict__ attn, float* __restrict__ out)
{
    extern __shared__ bf16 smB[];
    float* s_rs = (float*)(smB + 54272);          // [128] row sums
    const int rt = 15 - blockIdx.x;
    const int bh = blockIdx.y;
    const int b = bh >> 3, hh = bh & 7;
    const int r0 = rt * 128;
    const int tid = threadIdx.x, lane = tid & 31, w = tid >> 5;
    float* attn_base = attn + (size_t)bh * SEQ * SEQ;

    // upper-triangle zero-fill for these rows (final values, evict-first)
    const int zc = 1920 - r0;
    if (zc > 0) {
        const int zc4 = zc >> 2;
        for (int idx = tid; idx < 128 * zc4; idx += 256) {
            const int row = idx / zc4, c = (idx % zc4) * 4;
            stg_cs_z4(attn_base + (size_t)(r0 + row) * SEQ + r0 + 128 + c);
        }
    }

    // stage Q once, extract persistent A-frags
    {
        bf16* Th = smB;
        bf16* Tl = smB + 9216;
#pragma unroll
        for (int i = 0; i < 4; i++) {
            const int idx = i * 256 + tid;
            const int row = idx >> 3, q8 = (idx & 7) * 8;
            const size_t off = ((size_t)bh * SEQ + r0 + row) * 64 + q8;
            *(uint4*)(Th + row * 72 + q8) = *(const uint4*)(g_qh + off);
            *(uint4*)(Tl + row * 72 + q8) = *(const uint4*)(g_ql + off);
        }
    }
    __syncthreads();
    uint32_t qh[4][4], ql[4][4];
    {
        const int ar = lane & 15;
#pragma unroll
        for (int kc = 0; kc < 4; kc++) {
            const int ac = kc * 16 + ((lane >> 4) & 1) * 8;
            ldmA4(qh[kc], smB + (w * 16 + ar) * 72 + ac);
            ldmA4(ql[kc], smB + 9216 + (w * 16 + ar) * 72 + ac);
        }
    }
    __syncthreads();

    const int rlA = w * 16 + (lane >> 2), rlB = rlA + 8;

    auto load_k = [&](int jt, int st) {
        bf16* base = smB + st * 18432;
        const int j0 = jt * 128;
#pragma unroll
        for (int i = 0; i < 4; i++) {
            const int idx = i * 256 + tid;
            const int row = idx >> 3, q8 = (idx & 7) * 8;
            const size_t off = ((size_t)bh * SEQ + j0 + row) * 64 + q8;
            cp_async16(base + row * 72 + q8, g_kh + off);
            cp_async16(base + 9216 + row * 72 + q8, g_kl + off);
        }
    };
    auto load_v = [&](int jt) {
        bf16* Vh = smB + 36864;
        const int j0 = jt * 128;
#pragma unroll
        for (int i = 0; i < 4; i++) {
            const int idx = i * 256 + tid;
            const int d = idx >> 4, q8 = (idx & 15) * 8;
            const size_t off = ((size_t)bh * 64 + d) * SEQ + j0 + q8;
            cp_async16(Vh + d * 136 + q8, g_vth + off);
            cp_async16(Vh + 8704 + d * 136 + q8, g_vtl + off);
        }
    };

    // ================= phase A: rowsums =================
    {
        float rs0 = 0.f, rs1 = 0.f;
        load_k(0, 0);
        asm volatile("cp.async.commit_group;");
        for (int jt = 0; jt <= rt; jt++) {
            if (jt < rt) {
                load_k(jt + 1, (jt + 1) & 1);
                asm volatile("cp.async.commit_group;");
                asm volatile("cp.async.wait_group 1;");
            } else {
                asm volatile("cp.async.wait_group 0;");
            }
            __syncthreads();
            bf16* Kh = smB + (jt & 1) * 18432;
            const bool diag = (jt == rt);

#pragma unroll
            for (int nc = 0; nc < 4; nc++) {
                float S[4][4];
#pragma unroll
                for (int i = 0; i < 4; i++)
#pragma unroll
                    for (int c = 0; c < 4; c++) S[i][c] = 0.f;
#pragma unroll
                for (int kc = 0; kc < 4; kc++) {
                    uint32_t fbh[4][2], fbl[4][2];
#pragma unroll
                    for (int nf = 0; nf < 4; nf += 2) {
                        const bf16* pb = b4addr(Kh, nc * 32 + nf * 8, kc * 16, lane, 72);
                        ldmB4(&fbh[nf][0], pb);
                        ldmB4(&fbl[nf][0], pb + 9216);
                    }
#pragma unroll
                    for (int nf = 0; nf < 4; nf++) mma_bf16(S[nf], qh[kc], fbh[nf]);
#pragma unroll
                    for (int nf = 0; nf < 4; nf++) mma_bf16(S[nf], qh[kc], fbl[nf]);
#pragma unroll
                    for (int nf = 0; nf < 4; nf++) mma_bf16(S[nf], ql[kc], fbh[nf]);
                }
#pragma unroll
                for (int nf = 0; nf < 4; nf++) {
                    const int jl = nc * 32 + nf * 8 + (lane & 3) * 2;
                    float p0 = __expf(S[nf][0] * 0.125f);
                    float p1 = __expf(S[nf][1] * 0.125f);
                    float p2 = __expf(S[nf][2] * 0.125f);
                    float p3 = __expf(S[nf][3] * 0.125f);
                    if (diag) {
                        if (jl > rlA)     p0 = 0.f;
                        if (jl + 1 > rlA) p1 = 0.f;
                        if (jl > rlB)     p2 = 0.f;
                        if (jl + 1 > rlB) p3 = 0.f;
                    }
                    rs0 += p0 + p1;
                    rs1 += p2 + p3;
                }
            }
            __syncthreads();
        }
        rs0 += __shfl_xor_sync(~0u, rs0, 1); rs0 += __shfl_xor_sync(~0u, rs0, 2);
        rs1 += __shfl_xor_sync(~0u, rs1, 1); rs1 += __shfl_xor_sync(~0u, rs1, 2);
        if ((lane & 3) == 0) {
            s_rs[rlA] = rs0;
            s_rs[rlB] = rs1;
        }
        __syncthreads();
    }

    const float inv0 = 1.f / s_rs[rlA];
    const float inv1 = 1.f / s_rs[rlB];

    // ================= phase B: P write + PV =================
    float O[8][4];
#pragma unroll
    for (int i = 0; i < 8; i++)
#pragma unroll
        for (int c = 0; c < 4; c++) O[i][c] = 0.f;

    load_k(0, 0);
    asm volatile("cp.async.commit_group;");
    for (int jt = 0; jt <= rt; jt++) {
        load_v(jt);
        asm volatile("cp.async.commit_group;");
        if (jt < rt) {
            load_k(jt + 1, (jt + 1) & 1);
            asm volatile("cp.async.commit_group;");
            asm volatile("cp.async.wait_group 2;");
        } else {
            asm volatile("cp.async.wait_group 1;");
        }
        __syncthreads();
        bf16* Kh = smB + (jt & 1) * 18432;
        bf16* Vh = smB + 36864;
        const int j0 = jt * 128;
        const bool diag = (jt == rt);

#pragma unroll
        for (int nc = 0; nc < 4; nc++) {
            float S[4][4];
#pragma unroll
            for (int i = 0; i < 4; i++)
#pragma unroll
                for (int c = 0; c < 4; c++) S[i][c] = 0.f;
#pragma unroll
            for (int kc = 0; kc < 4; kc++) {
                uint32_t kbh[4][2], kbl[4][2];
#pragma unroll
                for (int nf = 0; nf < 4; nf += 2) {
                    const bf16* pb = b4addr(Kh, nc * 32 + nf * 8, kc * 16, lane, 72);
                    ldmB4(&kbh[nf][0], pb);
                    ldmB4(&kbl[nf][0], pb + 9216);
                }
#pragma unroll
                for (int nf = 0; nf < 4; nf++) mma_bf16(S[nf], qh[kc], kbh[nf]);
#pragma unroll
                for (int nf = 0; nf < 4; nf++) mma_bf16(S[nf], qh[kc], kbl[nf]);
#pragma unroll
                for (int nf = 0; nf < 4; nf++) mma_bf16(S[nf], ql[kc], kbh[nf]);
            }

            uint32_t pah[2][4], pal[2][4];
#pragma unroll
            for (int nf = 0; nf < 4; nf++) {
                const int jl = nc * 32 + nf * 8 + (lane & 3) * 2;
                float p0 = __expf(S[nf][0] * 0.125f);
                float p1 = __expf(S[nf][1] * 0.125f);
                float p2 = __expf(S[nf][2] * 0.125f);
                float p3 = __expf(S[nf][3] * 0.125f);
                if (diag) {
                    if (jl > rlA)     p0 = 0.f;
                    if (jl + 1 > rlA) p1 = 0.f;
                    if (jl > rlB)     p2 = 0.f;
                    if (jl + 1 > rlB) p3 = 0.f;
                }
                p0 *= inv0; p1 *= inv0; p2 *= inv1; p3 *= inv1;
                stg_cs_f2(attn_base + (size_t)(r0 + rlA) * SEQ + j0 + jl, p0, p1);
                stg_cs_f2(attn_base + (size_t)(r0 + rlB) * SEQ + j0 + jl, p2, p3);

                bf16 h0,l0,h1,l1,h2,l2,h3,l3;
                split2(p0, h0, l0); split2(p1, h1, l1);
                split2(p2, h2, l2); split2(p3, h3, l3);
                const int f = nf >> 1, sl = (nf & 1) * 2;
                pah[f][sl + 0] = packbf(h0, h1);
                pah[f][sl + 1] = packbf(h2, h3);
                pal[f][sl + 0] = packbf(l0, l1);
                pal[f][sl + 1] = packbf(l2, l3);
            }

            if (nc == 0) {
                if (jt < rt) asm volatile("cp.async.wait_group 1;");
                else         asm volatile("cp.async.wait_group 0;");
                __syncthreads();
            }

#pragma unroll
            for (int kf = 0; kf < 2; kf++) {
                const int kg = nc * 32 + kf * 16;
                uint32_t vbh[8][2], vbl[8][2];
#pragma unroll
                for (int nf = 0; nf < 8; nf += 2) {
                    const bf16* pv = b4addr(Vh, nf * 8, kg, lane, 136);
                    ldmB4(&vbh[nf][0], pv);
                    ldmB4(&vbl[nf][0], pv + 8704);
                }
#pragma unroll
                for (int nf = 0; nf < 8; nf++) mma_bf16(O[nf], pah[kf], vbh[nf]);
#pragma unroll
                for (int nf = 0; nf < 8; nf++) mma_bf16(O[nf], pah[kf], vbl[nf]);
#pragma unroll
                for (int nf = 0; nf < 8; nf++) mma_bf16(O[nf], pal[kf], vbh[nf]);
            }
        }
        __syncthreads();
    }

#pragma unroll
    for (int nf = 0; nf < 8; nf++) {
        const int d = nf * 8 + (lane & 3) * 2;
        const int s0 = r0 + rlA, s1 = r0 + rlB;
        float2 o0; o0.x = O[nf][0]; o0.y = O[nf][1];
        float2 o1; o1.x = O[nf][2]; o1.y = O[nf][3];
        *(float2*)(out + (((size_t)(b * SEQ + s0)) * NH + hh) * 64 + d) = o0;
        *(float2*)(out + (((size_t)(b * SEQ + s1)) * NH + hh) * 64 + d) = o1;
    }
}

extern "C" void kernel_launch(void* const* d_in, const int* in_sizes, int n_in,
                              void* d_out, int out_size)
{
    const float* x  = (const float*)d_in[0];
    const float* wq = (const float*)d_in[2];
    const float* bq = (const float*)d_in[3];
    const float* wk = (const float*)d_in[4];
    const float* bk = (const float*)d_in[5];
    const float* wv = (const float*)d_in[6];
    const float* bv = (const float*)d_in[7];

    float* out  = (float*)d_out;
    float* attn = out + (size_t)Bsz * SEQ * NH * 64;

    const int prep_items = Bsz*SEQ*CH + CH*1536;
    prep_kernel<<<(prep_items + 255) / 256, 256>>>(x, wq, wk, wv);

    cudaFuncSetAttribute(qkv_gemm, cudaFuncAttributeMaxDynamicSharedMemorySize, 81920);
    qkv_gemm<<<dim3(64, 12), 256, 81920>>>(bq, bk, bv);

    cudaFuncSetAttribute(attn_fused, cudaFuncAttributeMaxDynamicSharedMemorySize, 109056);
    attn_fused<<<dim3(16, 32), 256, 109056>>>(attn, out);
}